// round 14
// baseline (speedup 1.0000x reference)
#include <cuda_runtime.h>
#include <math.h>
#include <stdint.h>

#define B 2048
#define C 50257
#define THREADS 512
#define OCC 3
#define NBLK (148 * OCC)        // persistent, all wave-1 resident at 3 CTAs/SM
#define NWARP (THREADS / 32)
#define STAGE_F4 1024           // 16 KB per stage
#define STAGE_BYTES (STAGE_F4 * 16)
#define NSTG 12                 // 12*1024 = 12288 <= min n4 (12563) for all alignments

// Per-row partials + completion counter (device globals: allocation-guard-safe)
__device__ float g_l1[B];
__device__ float g_ce[B];
__device__ unsigned int g_count = 0;   // self-resetting via atomicInc wrap

__device__ __forceinline__ void elem(float x, float& sum, float& l1, float& es) {
    sum += x;
    l1 += fabsf(1.f - fmaxf(x, 0.f));   // == (x>0) ? |1-x| : 1  (exact)
    es += __expf(x);
}

__device__ __forceinline__ void elem4(const float4 v, float& s0, float& s1,
                                      float& l0, float& l1, float& e0, float& e1) {
    elem(v.x, s0, l0, e0);
    elem(v.y, s1, l1, e1);
    elem(v.z, s0, l0, e0);
    elem(v.w, s1, l1, e1);
}

__device__ __forceinline__ float wred(float v) {
    v += __shfl_xor_sync(0xffffffffu, v, 16);
    v += __shfl_xor_sync(0xffffffffu, v, 8);
    v += __shfl_xor_sync(0xffffffffu, v, 4);
    v += __shfl_xor_sync(0xffffffffu, v, 2);
    v += __shfl_xor_sync(0xffffffffu, v, 1);
    return v;
}

__device__ __forceinline__ uint32_t s2u(const void* p) {
    uint32_t a;
    asm("{ .reg .u64 t; cvta.to.shared.u64 t, %1; cvt.u32.u64 %0, t; }"
        : "=r"(a) : "l"(p));
    return a;
}

__device__ __forceinline__ void mbar_init(uint32_t mbar, uint32_t count) {
    asm volatile("mbarrier.init.shared.b64 [%0], %1;" :: "r"(mbar), "r"(count) : "memory");
}

__device__ __forceinline__ void mbar_expect_tx(uint32_t mbar, uint32_t bytes) {
    asm volatile("mbarrier.arrive.expect_tx.shared.b64 _, [%0], %1;"
                 :: "r"(mbar), "r"(bytes) : "memory");
}

__device__ __forceinline__ void mbar_wait(uint32_t mbar, uint32_t parity) {
    uint32_t done;
    asm volatile(
        "{\n\t.reg .pred p;\n\t"
        "mbarrier.try_wait.parity.acquire.cta.shared::cta.b64 p, [%1], %2;\n\t"
        "selp.b32 %0, 1, 0, p;\n\t}"
        : "=r"(done) : "r"(mbar), "r"(parity) : "memory");
    if (!done) {
        asm volatile(
            "{\n\t.reg .pred P1;\n"
            "WL_%=:\n\t"
            "mbarrier.try_wait.parity.acquire.cta.shared::cta.b64 P1, [%0], %1, 0x989680;\n\t"
            "@P1 bra WD_%=;\n\t"
            "bra WL_%=;\n"
            "WD_%=:\n\t}"
            :: "r"(mbar), "r"(parity) : "memory");
    }
}

__device__ __forceinline__ void bulk_g2s(uint32_t dst_smem, const void* src,
                                         uint32_t bytes, uint32_t mbar) {
    asm volatile(
        "cp.async.bulk.shared::cluster.global.mbarrier::complete_tx::bytes "
        "[%0], [%1], %2, [%3];"
        :: "r"(dst_smem), "l"(src), "r"(bytes), "r"(mbar) : "memory");
}

__global__ __launch_bounds__(THREADS, OCC)
void fused_kernel(const float* __restrict__ out, const int* __restrict__ labels,
                  float* __restrict__ res) {
    const int tid  = threadIdx.x;
    const int wid  = tid >> 5;
    const int lane = tid & 31;

    __shared__ __align__(1024) float4 buf[2][STAGE_F4];   // 32 KB double buffer
    __shared__ uint64_t mbar_s[2];
    __shared__ float sh_a[NWARP];
    __shared__ float sh_b[NWARP];
    __shared__ float sh_c[NWARP];

    const uint32_t mb0 = s2u(&mbar_s[0]);
    const uint32_t mb1 = s2u(&mbar_s[1]);
    const uint32_t bufa0 = s2u(&buf[0][0]);
    const uint32_t bufa1 = s2u(&buf[1][0]);

    if (tid == 0) {
        mbar_init(mb0, 1);
        mbar_init(mb1, 1);
    }
    __syncthreads();

    uint32_t ph0 = 0, ph1 = 0;   // per-slot phase parity

    for (int row = blockIdx.x; row < B; row += NBLK) {
        const float* rp = out + (long long)row * C;

        // Prefetch label + gathered logit early (only tid 0 needs them at the end)
        float g = 0.f;
        if (tid == 0) {
            g = __ldg(rp + __ldg(labels + row));
        }

        float sum0 = 0.f, sum1 = 0.f;
        float l10 = 0.f, l11 = 0.f;
        float es0 = 0.f, es1 = 0.f;

        // Alignment peel to 16B (row base only 4B-aligned: C odd)
        const int mis = (int)(((uintptr_t)rp >> 2) & 3);
        const int pre = (4 - mis) & 3;
        if (tid < pre) elem(__ldg(rp + tid), sum0, l10, es0);

        const float4* rp4 = (const float4*)(rp + pre);
        const int n4 = (C - pre) >> 2;

        // Pipeline prologue: fill both stages
        if (tid == 0) {
            mbar_expect_tx(mb0, STAGE_BYTES);
            bulk_g2s(bufa0, rp4, STAGE_BYTES, mb0);
            mbar_expect_tx(mb1, STAGE_BYTES);
            bulk_g2s(bufa1, rp4 + STAGE_F4, STAGE_BYTES, mb1);
        }

        // Main pipeline: 12 full stages of 1024 float4 (each thread eats 2)
        #pragma unroll 1
        for (int st = 0; st < NSTG; ++st) {
            const int slot = st & 1;
            if (slot == 0) { mbar_wait(mb0, ph0); ph0 ^= 1; }
            else           { mbar_wait(mb1, ph1); ph1 ^= 1; }

            float4 a = buf[slot][tid];
            float4 b = buf[slot][tid + THREADS];
            elem4(a, sum0, sum1, l10, l11, es0, es1);
            elem4(b, sum0, sum1, l10, l11, es0, es1);
            __syncthreads();   // all reads done before tid0 reissues this slot

            if (st + 2 < NSTG && tid == 0) {
                if (slot == 0) {
                    mbar_expect_tx(mb0, STAGE_BYTES);
                    bulk_g2s(bufa0, rp4 + (st + 2) * STAGE_F4, STAGE_BYTES, mb0);
                } else {
                    mbar_expect_tx(mb1, STAGE_BYTES);
                    bulk_g2s(bufa1, rp4 + (st + 2) * STAGE_F4, STAGE_BYTES, mb1);
                }
            }
        }

        // Remainder float4s (275-276 of them) via plain streaming loads
        for (int i = NSTG * STAGE_F4 + tid; i < n4; i += THREADS) {
            float4 a = __ldcs(rp4 + i);
            elem4(a, sum0, sum1, l10, l11, es0, es1);
        }
        // Scalar tail (< 4 elems)
        const int tail_start = pre + (n4 << 2);
        if (tid < C - tail_start) elem(__ldg(rp + tail_start + tid), sum0, l10, es0);

        // Shuffle-based block reduction (1 barrier)
        float s = wred(sum0 + sum1);
        float l = wred(l10 + l11);
        float e = wred(es0 + es1);
        if (lane == 0) { sh_a[wid] = s; sh_b[wid] = l; sh_c[wid] = e; }
        __syncthreads();

        if (wid == 0) {
            float rs = (lane < NWARP) ? sh_a[lane] : 0.f;
            float rl = (lane < NWARP) ? sh_b[lane] : 0.f;
            float re = (lane < NWARP) ? sh_c[lane] : 0.f;
            rs = wred(rs); rl = wred(rl); re = wred(re);

            if (lane == 0) {
                // remove generic term at label column, add the real one
                const float wrong = fabsf(1.f - fmaxf(g, 0.f));   // unscaled
                const float mean = rs * (1.f / (float)C);
                const float row_val = fmaxf(fabsf(mean), fabsf(g)) * 10.f;
                const float temp_out_lbl = (g > 0.f) ? -10.f * g : 0.f;
                const float right = fabsf(temp_out_lbl - row_val);
                g_l1[row] = (rl - wrong) * 10.f + right;
                g_ce[row] = logf(re) - g;
            }
        }
        __syncthreads();   // protect shared reuse next row iteration
    }

    // Completion: last of NBLK blocks does the deterministic final reduce
    __shared__ bool s_last;
    if (tid == 0) {
        __threadfence();
        s_last = (atomicInc(&g_count, NBLK - 1) == NBLK - 1);
    }
    __syncthreads();

    if (s_last) {
        float a = 0.f, b = 0.f;
        #pragma unroll
        for (int k = 0; k < B / THREADS; k++) {
            a += g_l1[tid + k * THREADS];
            b += g_ce[tid + k * THREADS];
        }
        __shared__ float fa[NWARP];
        __shared__ float fb[NWARP];
        a = wred(a);
        b = wred(b);
        if (lane == 0) { fa[wid] = a; fb[wid] = b; }
        __syncthreads();
        if (wid == 0) {
            float ra = (lane < NWARP) ? fa[lane] : 0.f;
            float rb = (lane < NWARP) ? fb[lane] : 0.f;
            ra = wred(ra); rb = wred(rb);
            if (lane == 0) {
                const float l1_mean = ra / ((float)B * (float)C);
                const float ce_mean = rb / (float)B;
                res[0] = 0.5f * l1_mean + 0.5f * ce_mean;
            }
        }
    }
}

extern "C" void kernel_launch(void* const* d_in, const int* in_sizes, int n_in,
                              void* d_out, int out_size) {
    const float* out = (const float*)d_in[0];
    const int* labels = (const int*)d_in[1];
    float* res = (float*)d_out;

    fused_kernel<<<NBLK, THREADS>>>(out, labels, res);
}

// round 15
// speedup vs baseline: 1.0652x; 1.0652x over previous
#include <cuda_runtime.h>
#include <math.h>
#include <stdint.h>

#define B 2048
#define C 50257
#define THREADS 512
#define OCC 3
#define NBLK (148 * OCC)        // persistent, all wave-1 resident at 3 CTAs/SM
#define NWARP (THREADS / 32)
// Guaranteed in-bounds unrolled region: n4 >= 12563 for every row alignment.
// 6 iterations x (4*THREADS) float4 = 12288 <= 12563.
#define FULL_ITERS 6
#define FULL_F4 (FULL_ITERS * 4 * THREADS)

// Per-row partials + completion counter (device globals: allocation-guard-safe)
__device__ float g_l1[B];
__device__ float g_ce[B];
__device__ unsigned int g_count = 0;   // self-resetting via atomicInc wrap

__device__ __forceinline__ void elem(float x, float& sum, float& l1, float& es) {
    sum += x;
    l1 += fabsf(1.f - fmaxf(x, 0.f));   // == (x>0) ? |1-x| : 1  (exact)
    es += __expf(x);
}

__device__ __forceinline__ void elem4(const float4 v, float& s0, float& s1,
                                      float& l0, float& l1, float& e0, float& e1) {
    elem(v.x, s0, l0, e0);
    elem(v.y, s1, l1, e1);
    elem(v.z, s0, l0, e0);
    elem(v.w, s1, l1, e1);
}

__device__ __forceinline__ float wred(float v) {
    v += __shfl_xor_sync(0xffffffffu, v, 16);
    v += __shfl_xor_sync(0xffffffffu, v, 8);
    v += __shfl_xor_sync(0xffffffffu, v, 4);
    v += __shfl_xor_sync(0xffffffffu, v, 2);
    v += __shfl_xor_sync(0xffffffffu, v, 1);
    return v;
}

__global__ __launch_bounds__(THREADS, OCC)
void fused_kernel(const float* __restrict__ out, const int* __restrict__ labels,
                  float* __restrict__ res) {
    const int tid  = threadIdx.x;
    const int wid  = tid >> 5;
    const int lane = tid & 31;

    __shared__ float sh_a[NWARP];
    __shared__ float sh_b[NWARP];
    __shared__ float sh_c[NWARP];

    for (int row = blockIdx.x; row < B; row += NBLK) {
        const float* rp = out + (long long)row * C;

        // Prefetch label + gathered logit early (only tid 0 needs them at the end)
        float g = 0.f;
        if (tid == 0) {
            g = __ldg(rp + __ldg(labels + row));
        }

        float sum0 = 0.f, sum1 = 0.f;
        float l10 = 0.f, l11 = 0.f;
        float es0 = 0.f, es1 = 0.f;

        // Alignment peel to 16B (row base only 4B-aligned: C odd)
        const int mis = (int)(((uintptr_t)rp >> 2) & 3);
        const int pre = (4 - mis) & 3;
        if (tid < pre) elem(__ldg(rp + tid), sum0, l10, es0);

        const float4* rp4 = (const float4*)(rp + pre);
        const int n4 = (C - pre) >> 2;

        // Hot region: 4 independent LDG.128/iter; unroll 2 lets ptxas hoist
        // the next quad's loads above the current consume chain.
        #pragma unroll 2
        for (int it = 0; it < FULL_ITERS; ++it) {
            const int i = it * (4 * THREADS) + tid;
            float4 a = __ldcs(rp4 + i);
            float4 b = __ldcs(rp4 + i + THREADS);
            float4 c = __ldcs(rp4 + i + 2 * THREADS);
            float4 d = __ldcs(rp4 + i + 3 * THREADS);
            elem4(a, sum0, sum1, l10, l11, es0, es1);
            elem4(b, sum0, sum1, l10, l11, es0, es1);
            elem4(c, sum0, sum1, l10, l11, es0, es1);
            elem4(d, sum0, sum1, l10, l11, es0, es1);
        }
        // Remainder float4s (< THREADS of them after the 12288 hot region)
        for (int i = FULL_F4 + tid; i < n4; i += THREADS) {
            float4 a = __ldcs(rp4 + i);
            elem4(a, sum0, sum1, l10, l11, es0, es1);
        }
        // Scalar tail (< 4 elems)
        const int tail_start = pre + (n4 << 2);
        if (tid < C - tail_start) elem(__ldg(rp + tail_start + tid), sum0, l10, es0);

        // Shuffle-based block reduction (1 barrier)
        float s = wred(sum0 + sum1);
        float l = wred(l10 + l11);
        float e = wred(es0 + es1);
        if (lane == 0) { sh_a[wid] = s; sh_b[wid] = l; sh_c[wid] = e; }
        __syncthreads();

        if (wid == 0) {
            float rs = (lane < NWARP) ? sh_a[lane] : 0.f;
            float rl = (lane < NWARP) ? sh_b[lane] : 0.f;
            float re = (lane < NWARP) ? sh_c[lane] : 0.f;
            rs = wred(rs); rl = wred(rl); re = wred(re);

            if (lane == 0) {
                // remove generic term at label column, add the real one
                const float wrong = fabsf(1.f - fmaxf(g, 0.f));   // unscaled
                const float mean = rs * (1.f / (float)C);
                const float row_val = fmaxf(fabsf(mean), fabsf(g)) * 10.f;
                const float temp_out_lbl = (g > 0.f) ? -10.f * g : 0.f;
                const float right = fabsf(temp_out_lbl - row_val);
                g_l1[row] = (rl - wrong) * 10.f + right;
                g_ce[row] = logf(re) - g;
            }
        }
        __syncthreads();   // protect shared reuse next row iteration
    }

    // Completion: last of NBLK blocks does the deterministic final reduce
    __shared__ bool s_last;
    if (tid == 0) {
        __threadfence();
        s_last = (atomicInc(&g_count, NBLK - 1) == NBLK - 1);
    }
    __syncthreads();

    if (s_last) {
        float a = 0.f, b = 0.f;
        #pragma unroll
        for (int k = 0; k < B / THREADS; k++) {
            a += g_l1[tid + k * THREADS];
            b += g_ce[tid + k * THREADS];
        }
        __shared__ float fa[NWARP];
        __shared__ float fb[NWARP];
        a = wred(a);
        b = wred(b);
        if (lane == 0) { fa[wid] = a; fb[wid] = b; }
        __syncthreads();
        if (wid == 0) {
            float ra = (lane < NWARP) ? fa[lane] : 0.f;
            float rb = (lane < NWARP) ? fb[lane] : 0.f;
            ra = wred(ra); rb = wred(rb);
            if (lane == 0) {
                const float l1_mean = ra / ((float)B * (float)C);
                const float ce_mean = rb / (float)B;
                res[0] = 0.5f * l1_mean + 0.5f * ce_mean;
            }
        }
    }
}

extern "C" void kernel_launch(void* const* d_in, const int* in_sizes, int n_in,
                              void* d_out, int out_size) {
    const float* out = (const float*)d_in[0];
    const int* labels = (const int*)d_in[1];
    float* res = (float*)d_out;

    fused_kernel<<<NBLK, THREADS>>>(out, labels, res);
}